// round 1
// baseline (speedup 1.0000x reference)
#include <cuda_runtime.h>
#include <math.h>

// ---------------------------------------------------------------------------
// Problem constants (from reference setup_inputs)
// ---------------------------------------------------------------------------
#define NN   50000
#define FIN  256
#define HH   128
#define CC   64
#define EMAX 1600000

// ---------------------------------------------------------------------------
// Scratch pool layout (floats). Single __device__ global, offset-addressed.
// ---------------------------------------------------------------------------
constexpr long long OFF_XL1 = 0;                                   // NN*HH
constexpr long long OFF_XR1 = (long long)NN * HH;                  // NN*HH
constexpr long long OFF_H   = 2LL * NN * HH;                       // NN*HH (agg1 -> h)
constexpr long long OFF_XL2 = 3LL * NN * HH;                       // NN*CC
constexpr long long OFF_XR2 = OFF_XL2 + (long long)NN * CC;        // NN*CC
constexpr long long OFF_E   = OFF_XR2 + (long long)NN * CC;        // EMAX
constexpr long long OFF_M   = OFF_E + EMAX;                        // NN
constexpr long long OFF_S   = OFF_M + NN;                          // NN
constexpr long long POOL_SZ = OFF_S + NN;

__device__ float g_pool[POOL_SZ];

// ---------------------------------------------------------------------------
// Helpers
// ---------------------------------------------------------------------------
__device__ __forceinline__ void atomicMaxF(float* addr, float value) {
    // IEEE-754 ordered-int trick, sign-split
    if (value >= 0.0f)
        atomicMax((int*)addr, __float_as_int(value));
    else
        atomicMin((unsigned int*)addr, (unsigned int)__float_as_int(value));
}

__device__ __forceinline__ float lrelu(float z) {
    return z > 0.0f ? z : 0.2f * z;
}

// ---------------------------------------------------------------------------
// SGEMM: C[N,Fout] = A[N,K] @ W[K,Fout]. 64x64 tile, BK=16, 4x4 microtile.
// A/C can live in g_pool (offset >= 0) or be external pointers.
// ---------------------------------------------------------------------------
__global__ void sgemm_kernel(const float* __restrict__ Ain, long long a_off,
                             const float* __restrict__ W,
                             long long c_off, int N, int K, int Fout) {
    const float* A = (a_off >= 0) ? (g_pool + a_off) : Ain;
    float* Cm = g_pool + c_off;

    __shared__ float As[16][64 + 4];
    __shared__ float Ws[16][64];

    int t = threadIdx.x;            // 0..255
    int row0 = blockIdx.x * 64;
    int col0 = blockIdx.y * 64;
    int tx = t & 15, ty = t >> 4;

    float acc[4][4] = {};

    for (int k0 = 0; k0 < K; k0 += 16) {
        // Load A tile 64x16 (transposed into smem)
        {
            int m  = t >> 2;          // 0..63
            int kq = (t & 3) * 4;     // 0,4,8,12
            int gr = row0 + m;
            float4 v = make_float4(0.f, 0.f, 0.f, 0.f);
            if (gr < N)
                v = *(const float4*)(A + (size_t)gr * K + k0 + kq);
            As[kq + 0][m] = v.x; As[kq + 1][m] = v.y;
            As[kq + 2][m] = v.z; As[kq + 3][m] = v.w;
        }
        // Load W tile 16x64
        {
            int kk = t >> 4;          // 0..15
            int nq = (t & 15) * 4;    // 0..60
            float4 v = *(const float4*)(W + (size_t)(k0 + kk) * Fout + col0 + nq);
            *(float4*)&Ws[kk][nq] = v;
        }
        __syncthreads();

        #pragma unroll
        for (int kk = 0; kk < 16; ++kk) {
            float ra[4], rb[4];
            #pragma unroll
            for (int i = 0; i < 4; i++) ra[i] = As[kk][ty * 4 + i];
            #pragma unroll
            for (int j = 0; j < 4; j++) rb[j] = Ws[kk][tx * 4 + j];
            #pragma unroll
            for (int i = 0; i < 4; i++)
                #pragma unroll
                for (int j = 0; j < 4; j++)
                    acc[i][j] += ra[i] * rb[j];
        }
        __syncthreads();
    }

    #pragma unroll
    for (int i = 0; i < 4; i++) {
        int gr = row0 + ty * 4 + i;
        if (gr < N) {
            float4 v = make_float4(acc[i][0], acc[i][1], acc[i][2], acc[i][3]);
            *(float4*)(Cm + (size_t)gr * Fout + col0 + tx * 4) = v;
        }
    }
}

// ---------------------------------------------------------------------------
// Init: zero aggregate buffer (pool or external), set m=-inf, s=0
// ---------------------------------------------------------------------------
__global__ void init_kernel(long long agg_off, float* __restrict__ outp, long long nf) {
    float* agg = (agg_off >= 0) ? (g_pool + agg_off) : outp;
    long long stride = (long long)gridDim.x * blockDim.x;
    for (long long i = (long long)blockIdx.x * blockDim.x + threadIdx.x; i < nf; i += stride) {
        agg[i] = 0.0f;
        if (i < NN) {
            g_pool[OFF_M + i] = -INFINITY;
            g_pool[OFF_S + i] = 0.0f;
        }
    }
}

// ---------------------------------------------------------------------------
// Edge logits: e[i] = sum_f att[f] * lrelu(xl[src,f] + xr[dst,f]);
// also atomicMax into m[dst]. One warp per edge.
// ---------------------------------------------------------------------------
template<int F>
__global__ void edge_logits_kernel(const int* __restrict__ src,
                                   const int* __restrict__ dst,
                                   int E, long long xl_off, long long xr_off,
                                   const float* __restrict__ att) {
    int wid  = (int)(((long long)blockIdx.x * blockDim.x + threadIdx.x) >> 5);
    int lane = threadIdx.x & 31;
    if (wid >= E) return;

    const float* xl = g_pool + xl_off;
    const float* xr = g_pool + xr_off;
    int s = src[wid], d = dst[wid];

    float sum;
    if (F == 128) {
        float4 a = *(const float4*)(xl + (size_t)s * F + lane * 4);
        float4 b = *(const float4*)(xr + (size_t)d * F + lane * 4);
        float4 w = *(const float4*)(att + lane * 4);
        sum = lrelu(a.x + b.x) * w.x + lrelu(a.y + b.y) * w.y +
              lrelu(a.z + b.z) * w.z + lrelu(a.w + b.w) * w.w;
    } else { // F == 64
        float2 a = *(const float2*)(xl + (size_t)s * F + lane * 2);
        float2 b = *(const float2*)(xr + (size_t)d * F + lane * 2);
        float2 w = *(const float2*)(att + lane * 2);
        sum = lrelu(a.x + b.x) * w.x + lrelu(a.y + b.y) * w.y;
    }
    #pragma unroll
    for (int o = 16; o; o >>= 1) sum += __shfl_xor_sync(0xFFFFFFFFu, sum, o);

    if (lane == 0) {
        g_pool[OFF_E + wid] = sum;
        atomicMaxF(g_pool + OFF_M + d, sum);
    }
}

// ---------------------------------------------------------------------------
// exp pass: a = exp(e - m[dst]); e[i] = a; s[dst] += a
// ---------------------------------------------------------------------------
__global__ void edge_exp_kernel(const int* __restrict__ dst, int E) {
    int i = blockIdx.x * blockDim.x + threadIdx.x;
    if (i >= E) return;
    int d = dst[i];
    float a = expf(g_pool[OFF_E + i] - g_pool[OFF_M + d]);
    g_pool[OFF_E + i] = a;
    atomicAdd(&g_pool[OFF_S + d], a);
}

// ---------------------------------------------------------------------------
// Aggregate: out[dst] += (a / (s[dst]+eps)) * xl[src]. Warp per edge,
// vectorized red.global.add (sm_90+).
// ---------------------------------------------------------------------------
template<int F>
__global__ void edge_aggr_kernel(const int* __restrict__ src,
                                 const int* __restrict__ dst,
                                 int E, long long xl_off,
                                 float* __restrict__ outp, long long out_off) {
    int wid  = (int)(((long long)blockIdx.x * blockDim.x + threadIdx.x) >> 5);
    int lane = threadIdx.x & 31;
    if (wid >= E) return;

    float* out = (out_off >= 0) ? (g_pool + out_off) : outp;
    const float* xl = g_pool + xl_off;
    int s = src[wid], d = dst[wid];

    float alpha;
    if (lane == 0)
        alpha = g_pool[OFF_E + wid] / (g_pool[OFF_S + d] + 1e-16f);
    alpha = __shfl_sync(0xFFFFFFFFu, alpha, 0);

    if (F == 128) {
        float4 a = *(const float4*)(xl + (size_t)s * F + lane * 4);
        float* p = out + (size_t)d * F + lane * 4;
        asm volatile("red.global.add.v4.f32 [%0], {%1,%2,%3,%4};"
                     :: "l"(p), "f"(a.x * alpha), "f"(a.y * alpha),
                        "f"(a.z * alpha), "f"(a.w * alpha) : "memory");
    } else { // F == 64
        float2 a = *(const float2*)(xl + (size_t)s * F + lane * 2);
        float* p = out + (size_t)d * F + lane * 2;
        asm volatile("red.global.add.v2.f32 [%0], {%1,%2};"
                     :: "l"(p), "f"(a.x * alpha), "f"(a.y * alpha) : "memory");
    }
}

// ---------------------------------------------------------------------------
// Finalize layer1: h = relu(agg + b1), in place in pool
// ---------------------------------------------------------------------------
__global__ void finalize1_kernel(const float* __restrict__ b) {
    long long n = (long long)NN * HH;
    long long stride = (long long)gridDim.x * blockDim.x;
    for (long long i = (long long)blockIdx.x * blockDim.x + threadIdx.x; i < n; i += stride) {
        float v = g_pool[OFF_H + i] + b[i & (HH - 1)];
        g_pool[OFF_H + i] = v > 0.0f ? v : 0.0f;
    }
}

// Finalize layer2: out += b2
__global__ void finalize2_kernel(float* __restrict__ out, const float* __restrict__ b) {
    long long n = (long long)NN * CC;
    long long stride = (long long)gridDim.x * blockDim.x;
    for (long long i = (long long)blockIdx.x * blockDim.x + threadIdx.x; i < n; i += stride)
        out[i] += b[i & (CC - 1)];
}

// ---------------------------------------------------------------------------
// Host launch
// ---------------------------------------------------------------------------
extern "C" void kernel_launch(void* const* d_in, const int* in_sizes, int n_in,
                              void* d_out, int out_size) {
    const float* x    = (const float*)d_in[0];
    const int*   ei   = (const int*)d_in[1];
    const float* Wl1  = (const float*)d_in[2];
    const float* Wr1  = (const float*)d_in[3];
    const float* att1 = (const float*)d_in[4];
    const float* b1   = (const float*)d_in[5];
    const float* Wl2  = (const float*)d_in[6];
    const float* Wr2  = (const float*)d_in[7];
    const float* att2 = (const float*)d_in[8];
    const float* b2   = (const float*)d_in[9];
    float* out = (float*)d_out;

    int E = in_sizes[1] / 2;
    const int* srcp = ei;
    const int* dstp = ei + E;

    int edgeBlocksWarp = (E + 7) / 8;          // 8 warps / 256-thread block
    int edgeBlocksThr  = (E + 255) / 256;

    // ======================= Layer 1 =======================
    {
        dim3 grid((NN + 63) / 64, HH / 64);
        sgemm_kernel<<<grid, 256>>>(x, -1, Wl1, OFF_XL1, NN, FIN, HH);
        sgemm_kernel<<<grid, 256>>>(x, -1, Wr1, OFF_XR1, NN, FIN, HH);
    }
    {
        long long nf = (long long)NN * HH;
        init_kernel<<<(int)((nf + 255) / 256), 256>>>(OFF_H, nullptr, nf);
    }
    edge_logits_kernel<HH><<<edgeBlocksWarp, 256>>>(srcp, dstp, E, OFF_XL1, OFF_XR1, att1);
    edge_exp_kernel<<<edgeBlocksThr, 256>>>(dstp, E);
    edge_aggr_kernel<HH><<<edgeBlocksWarp, 256>>>(srcp, dstp, E, OFF_XL1, nullptr, OFF_H);
    finalize1_kernel<<<(int)(((long long)NN * HH + 255) / 256), 256>>>(b1);

    // ======================= Layer 2 =======================
    {
        dim3 grid((NN + 63) / 64, CC / 64);
        sgemm_kernel<<<grid, 256>>>(nullptr, OFF_H, Wl2, OFF_XL2, NN, HH, CC);
        sgemm_kernel<<<grid, 256>>>(nullptr, OFF_H, Wr2, OFF_XR2, NN, HH, CC);
    }
    {
        long long nf = (long long)NN * CC;
        init_kernel<<<(int)((nf + 255) / 256), 256>>>(-1, out, nf);
    }
    edge_logits_kernel<CC><<<edgeBlocksWarp, 256>>>(srcp, dstp, E, OFF_XL2, OFF_XR2, att2);
    edge_exp_kernel<<<edgeBlocksThr, 256>>>(dstp, E);
    edge_aggr_kernel<CC><<<edgeBlocksWarp, 256>>>(srcp, dstp, E, OFF_XL2, out, -1);
    finalize2_kernel<<<(int)(((long long)NN * CC + 255) / 256), 256>>>(out, b2);
}

// round 2
// speedup vs baseline: 1.9942x; 1.9942x over previous
#include <cuda_runtime.h>
#include <math.h>

// ---------------------------------------------------------------------------
// Problem constants
// ---------------------------------------------------------------------------
#define NN   50000
#define FIN  256
#define HH   128
#define CC   64
#define EMAX 1600000

// ---------------------------------------------------------------------------
// Scratch (all static __device__, no allocation)
// ---------------------------------------------------------------------------
constexpr long long OFF_XL1 = 0;                                   // NN*HH
constexpr long long OFF_XR1 = (long long)NN * HH;                  // NN*HH
constexpr long long OFF_H   = 2LL * NN * HH;                       // NN*HH
constexpr long long OFF_XL2 = 3LL * NN * HH;                       // NN*CC
constexpr long long OFF_XR2 = OFF_XL2 + (long long)NN * CC;        // NN*CC
constexpr long long POOL_SZ = OFF_XR2 + (long long)NN * CC;

__device__ float g_pool[POOL_SZ];

__device__ int g_cnt[NN];
__device__ int g_off[NN + 1];
__device__ int g_cur[NN];
__device__ int g_ssrc[EMAX];   // src ids sorted by dst

// ---------------------------------------------------------------------------
// CSR construction
// ---------------------------------------------------------------------------
__global__ void zero_cnt_kernel() {
    int i = blockIdx.x * blockDim.x + threadIdx.x;
    if (i < NN) g_cnt[i] = 0;
}

__global__ void hist_kernel(const int* __restrict__ dst, int E) {
    int i = blockIdx.x * blockDim.x + threadIdx.x;
    if (i < E) atomicAdd(&g_cnt[dst[i]], 1);
}

// Single-block exclusive scan over g_cnt -> g_off (and g_cur copy)
__global__ void scan_kernel(int E) {
    __shared__ int warp_tot[32];
    __shared__ int carry_sh;
    int tid = threadIdx.x;
    int lane = tid & 31, wid = tid >> 5;
    if (tid == 0) carry_sh = 0;
    __syncthreads();

    for (int base = 0; base < NN; base += 1024) {
        int carry = carry_sh;
        int idx = base + tid;
        int v = (idx < NN) ? g_cnt[idx] : 0;
        // warp inclusive scan
        int x = v;
        #pragma unroll
        for (int o = 1; o < 32; o <<= 1) {
            int t = __shfl_up_sync(0xFFFFFFFFu, x, o);
            if (lane >= o) x += t;
        }
        if (lane == 31) warp_tot[wid] = x;
        __syncthreads();
        if (wid == 0) {
            int w = warp_tot[lane];
            int wx = w;
            #pragma unroll
            for (int o = 1; o < 32; o <<= 1) {
                int t = __shfl_up_sync(0xFFFFFFFFu, wx, o);
                if (lane >= o) wx += t;
            }
            warp_tot[lane] = wx - w;   // exclusive warp prefix
        }
        __syncthreads();
        int excl = x - v + warp_tot[wid] + carry;
        if (idx < NN) { g_off[idx] = excl; g_cur[idx] = excl; }
        __syncthreads();
        if (tid == 1023) carry_sh = excl + v;
        __syncthreads();
    }
    if (tid == 0) g_off[NN] = E;
}

__global__ void scatter_kernel(const int* __restrict__ src,
                               const int* __restrict__ dst, int E) {
    int i = blockIdx.x * blockDim.x + threadIdx.x;
    if (i < E) {
        int d = dst[i];
        int pos = atomicAdd(&g_cur[d], 1);
        g_ssrc[pos] = src[i];
    }
}

// ---------------------------------------------------------------------------
// SGEMM: C[N,Fout] = A[N,K] @ W[K,Fout]. 128xTN tile, BK=8, 8x(TN/16) micro.
// ---------------------------------------------------------------------------
template<int TN>
__global__ __launch_bounds__(256)
void sgemm_kernel(const float* __restrict__ Ain, long long a_off,
                  const float* __restrict__ W, long long c_off,
                  int N, int K, int Fout) {
    constexpr int TM = 128, BK = 8;
    constexpr int MN = TN / 16;     // cols per thread (8 or 4)
    const float* A = (a_off >= 0) ? (g_pool + a_off) : Ain;
    float* C = g_pool + c_off;

    __shared__ float As[BK][TM];
    __shared__ float Ws[BK][TN];

    int t = threadIdx.x;
    int row0 = blockIdx.x * TM;
    int col0 = blockIdx.y * TN;
    int tx = t & 15, ty = t >> 4;

    float acc[8][MN];
    #pragma unroll
    for (int i = 0; i < 8; i++)
        #pragma unroll
        for (int j = 0; j < MN; j++) acc[i][j] = 0.0f;

    for (int k0 = 0; k0 < K; k0 += BK) {
        // A tile: 128 rows x 8 k = 256 float4, one per thread (transposed)
        {
            int r = t >> 1, kq = (t & 1) * 4;
            int gr = row0 + r;
            float4 v = make_float4(0.f, 0.f, 0.f, 0.f);
            if (gr < N) v = *(const float4*)(A + (size_t)gr * K + k0 + kq);
            As[kq + 0][r] = v.x; As[kq + 1][r] = v.y;
            As[kq + 2][r] = v.z; As[kq + 3][r] = v.w;
        }
        // W tile: 8 rows x TN = 2*TN float4
        {
            constexpr int NV = 2 * TN;
            if (t < NV) {
                int kk = t / (TN / 4);
                int nq = (t % (TN / 4)) * 4;
                *(float4*)&Ws[kk][nq] =
                    *(const float4*)(W + (size_t)(k0 + kk) * Fout + col0 + nq);
            }
        }
        __syncthreads();

        #pragma unroll
        for (int kk = 0; kk < BK; kk++) {
            float ra[8], rb[MN];
            *(float4*)&ra[0] = *(const float4*)&As[kk][ty * 8];
            *(float4*)&ra[4] = *(const float4*)&As[kk][ty * 8 + 4];
            *(float4*)&rb[0] = *(const float4*)&Ws[kk][tx * MN];
            if (MN == 8)
                *(float4*)&rb[4] = *(const float4*)&Ws[kk][tx * MN + 4];
            #pragma unroll
            for (int i = 0; i < 8; i++)
                #pragma unroll
                for (int j = 0; j < MN; j++)
                    acc[i][j] += ra[i] * rb[j];
        }
        __syncthreads();
    }

    #pragma unroll
    for (int i = 0; i < 8; i++) {
        int gr = row0 + ty * 8 + i;
        if (gr < N) {
            float* cp = C + (size_t)gr * Fout + col0 + tx * MN;
            *(float4*)cp = make_float4(acc[i][0], acc[i][1], acc[i][2], acc[i][3]);
            if (MN == 8)
                *(float4*)(cp + 4) = make_float4(acc[i][4], acc[i][5], acc[i][6], acc[i][7]);
        }
    }
}

// ---------------------------------------------------------------------------
// Fused per-node kernel: one warp per dst node, single pass online softmax.
// out[node] = (sum_i exp(e_i - m) * xl[src_i]) / (sum_i exp(e_i - m) + eps) + bias
// ---------------------------------------------------------------------------
__device__ __forceinline__ float lrelu(float z) {
    return z > 0.0f ? z : 0.2f * z;
}

template<int F, bool RELU>
__global__ __launch_bounds__(256)
void node_kernel(long long xl_off, long long xr_off,
                 const float* __restrict__ att,
                 const float* __restrict__ bias,
                 float* __restrict__ outp, long long out_off) {
    int node = (int)(((long long)blockIdx.x * blockDim.x + threadIdx.x) >> 5);
    int lane = threadIdx.x & 31;
    if (node >= NN) return;

    const float* xl = g_pool + xl_off;
    const float* xr = g_pool + xr_off;
    float* out = (out_off >= 0) ? (g_pool + out_off) : outp;

    int s0 = g_off[node], s1 = g_off[node + 1];

    if (F == 128) {
        float4 xr4 = *(const float4*)(xr + (size_t)node * F + lane * 4);
        float4 at4 = *(const float4*)(att + lane * 4);
        float4 acc = make_float4(0.f, 0.f, 0.f, 0.f);
        float m = -INFINITY, ssum = 0.0f;

        for (int base = s0; base < s1; base += 32) {
            int n = min(32, s1 - base);
            int sid = (base + lane < s1) ? g_ssrc[base + lane] : 0;
            for (int j = 0; j < n; j++) {
                int sj = __shfl_sync(0xFFFFFFFFu, sid, j);
                float4 a = *(const float4*)(xl + (size_t)sj * F + lane * 4);
                float part = lrelu(a.x + xr4.x) * at4.x + lrelu(a.y + xr4.y) * at4.y
                           + lrelu(a.z + xr4.z) * at4.z + lrelu(a.w + xr4.w) * at4.w;
                #pragma unroll
                for (int o = 16; o; o >>= 1)
                    part += __shfl_xor_sync(0xFFFFFFFFu, part, o);
                float e = part;   // same on all lanes
                if (e > m) {
                    float sc = __expf(m - e);   // 0 on first edge (m=-inf)
                    ssum = ssum * sc + 1.0f;
                    acc.x = acc.x * sc + a.x;
                    acc.y = acc.y * sc + a.y;
                    acc.z = acc.z * sc + a.z;
                    acc.w = acc.w * sc + a.w;
                    m = e;
                } else {
                    float w = __expf(e - m);
                    ssum += w;
                    acc.x += w * a.x; acc.y += w * a.y;
                    acc.z += w * a.z; acc.w += w * a.w;
                }
            }
        }
        float inv = 1.0f / (ssum + 1e-16f);
        float4 bb = *(const float4*)(bias + lane * 4);
        float4 o;
        o.x = acc.x * inv + bb.x; o.y = acc.y * inv + bb.y;
        o.z = acc.z * inv + bb.z; o.w = acc.w * inv + bb.w;
        if (RELU) {
            o.x = fmaxf(o.x, 0.f); o.y = fmaxf(o.y, 0.f);
            o.z = fmaxf(o.z, 0.f); o.w = fmaxf(o.w, 0.f);
        }
        *(float4*)(out + (size_t)node * F + lane * 4) = o;
    } else { // F == 64
        float2 xr2 = *(const float2*)(xr + (size_t)node * F + lane * 2);
        float2 at2 = *(const float2*)(att + lane * 2);
        float2 acc = make_float2(0.f, 0.f);
        float m = -INFINITY, ssum = 0.0f;

        for (int base = s0; base < s1; base += 32) {
            int n = min(32, s1 - base);
            int sid = (base + lane < s1) ? g_ssrc[base + lane] : 0;
            for (int j = 0; j < n; j++) {
                int sj = __shfl_sync(0xFFFFFFFFu, sid, j);
                float2 a = *(const float2*)(xl + (size_t)sj * F + lane * 2);
                float part = lrelu(a.x + xr2.x) * at2.x + lrelu(a.y + xr2.y) * at2.y;
                #pragma unroll
                for (int o = 16; o; o >>= 1)
                    part += __shfl_xor_sync(0xFFFFFFFFu, part, o);
                float e = part;
                if (e > m) {
                    float sc = __expf(m - e);
                    ssum = ssum * sc + 1.0f;
                    acc.x = acc.x * sc + a.x;
                    acc.y = acc.y * sc + a.y;
                    m = e;
                } else {
                    float w = __expf(e - m);
                    ssum += w;
                    acc.x += w * a.x; acc.y += w * a.y;
                }
            }
        }
        float inv = 1.0f / (ssum + 1e-16f);
        float2 bb = *(const float2*)(bias + lane * 2);
        float2 o;
        o.x = acc.x * inv + bb.x; o.y = acc.y * inv + bb.y;
        if (RELU) { o.x = fmaxf(o.x, 0.f); o.y = fmaxf(o.y, 0.f); }
        *(float2*)(out + (size_t)node * F + lane * 2) = o;
    }
}

// ---------------------------------------------------------------------------
// Host launch
// ---------------------------------------------------------------------------
extern "C" void kernel_launch(void* const* d_in, const int* in_sizes, int n_in,
                              void* d_out, int out_size) {
    const float* x    = (const float*)d_in[0];
    const int*   ei   = (const int*)d_in[1];
    const float* Wl1  = (const float*)d_in[2];
    const float* Wr1  = (const float*)d_in[3];
    const float* att1 = (const float*)d_in[4];
    const float* b1   = (const float*)d_in[5];
    const float* Wl2  = (const float*)d_in[6];
    const float* Wr2  = (const float*)d_in[7];
    const float* att2 = (const float*)d_in[8];
    const float* b2   = (const float*)d_in[9];
    float* out = (float*)d_out;

    int E = in_sizes[1] / 2;
    const int* srcp = ei;
    const int* dstp = ei + E;

    int eBlocks = (E + 255) / 256;
    int nodeWarpBlocks = (NN * 32 + 255) / 256;

    // ---- CSR build (shared by both layers) ----
    zero_cnt_kernel<<<(NN + 255) / 256, 256>>>();
    hist_kernel<<<eBlocks, 256>>>(dstp, E);
    scan_kernel<<<1, 1024>>>(E);
    scatter_kernel<<<eBlocks, 256>>>(srcp, dstp, E);

    // ---- Layer 1 ----
    {
        dim3 grid((NN + 127) / 128, HH / 128);
        sgemm_kernel<128><<<grid, 256>>>(x, -1, Wl1, OFF_XL1, NN, FIN, HH);
        sgemm_kernel<128><<<grid, 256>>>(x, -1, Wr1, OFF_XR1, NN, FIN, HH);
    }
    node_kernel<128, true><<<nodeWarpBlocks, 256>>>(OFF_XL1, OFF_XR1, att1, b1,
                                                    nullptr, OFF_H);

    // ---- Layer 2 ----
    {
        dim3 grid((NN + 127) / 128, CC / 64);
        sgemm_kernel<64><<<grid, 256>>>(nullptr, OFF_H, Wl2, OFF_XL2, NN, HH, CC);
        sgemm_kernel<64><<<grid, 256>>>(nullptr, OFF_H, Wr2, OFF_XR2, NN, HH, CC);
    }
    node_kernel<64, false><<<nodeWarpBlocks, 256>>>(OFF_XL2, OFF_XR2, att2, b2,
                                                    out, -1);
}

// round 3
// speedup vs baseline: 2.2672x; 1.1369x over previous
#include <cuda_runtime.h>
#include <cuda_bf16.h>
#include <math.h>

// ---------------------------------------------------------------------------
// Problem constants
// ---------------------------------------------------------------------------
#define NN   50000
#define FIN  256
#define HH   128
#define CC   64
#define EMAX 1600000
#define NBLK 196              // ceil(NN/256)

// ---------------------------------------------------------------------------
// Scratch (static __device__, no allocation)
// ---------------------------------------------------------------------------
constexpr long long OFF_XL1 = 0;
constexpr long long OFF_XR1 = (long long)NN * HH;
constexpr long long OFF_H   = 2LL * NN * HH;
constexpr long long OFF_XL2 = 3LL * NN * HH;
constexpr long long OFF_XR2 = OFF_XL2 + (long long)NN * CC;
constexpr long long POOL_SZ = OFF_XR2 + (long long)NN * CC;

__device__ float g_pool[POOL_SZ];

__device__ int g_cnt[NN];
__device__ int g_off[NN + 1];
__device__ int g_cur[NN];
__device__ int g_bsum[256];
__device__ int g_ssrc[EMAX];

// ---------------------------------------------------------------------------
// CSR construction
// ---------------------------------------------------------------------------
__global__ void zero_cnt_kernel() {
    int i = blockIdx.x * blockDim.x + threadIdx.x;
    if (i < NN) g_cnt[i] = 0;
}

__global__ void hist_kernel(const int* __restrict__ dst, int E) {
    int i0 = (blockIdx.x * blockDim.x + threadIdx.x) * 4;
    #pragma unroll
    for (int j = 0; j < 4; j++) {
        int i = i0 + j;
        if (i < E) atomicAdd(&g_cnt[dst[i]], 1);
    }
}

// block-local exclusive scan of g_cnt -> g_off, block totals -> g_bsum
__global__ void scan1_kernel() {
    __shared__ int wt[8];
    int t = threadIdx.x, lane = t & 31, wid = t >> 5;
    int idx = blockIdx.x * 256 + t;
    int v = (idx < NN) ? g_cnt[idx] : 0;
    int x = v;
    #pragma unroll
    for (int o = 1; o < 32; o <<= 1) {
        int tmp = __shfl_up_sync(0xFFFFFFFFu, x, o);
        if (lane >= o) x += tmp;
    }
    if (lane == 31) wt[wid] = x;
    __syncthreads();
    if (wid == 0 && lane < 8) {
        int w = wt[lane], wx = w;
        #pragma unroll
        for (int o = 1; o < 8; o <<= 1) {
            int tmp = __shfl_up_sync(0xFFu, wx, o);
            if (lane >= o) wx += tmp;
        }
        wt[lane] = wx - w;
    }
    __syncthreads();
    int excl = x - v + wt[wid];
    if (idx < NN) g_off[idx] = excl;
    if (t == 255) g_bsum[blockIdx.x] = excl + v;
}

// single block: exclusive scan of 196 block sums
__global__ void scan2_kernel() {
    __shared__ int wt[8];
    int t = threadIdx.x, lane = t & 31, wid = t >> 5;
    int v = (t < NBLK) ? g_bsum[t] : 0;
    int x = v;
    #pragma unroll
    for (int o = 1; o < 32; o <<= 1) {
        int tmp = __shfl_up_sync(0xFFFFFFFFu, x, o);
        if (lane >= o) x += tmp;
    }
    if (lane == 31) wt[wid] = x;
    __syncthreads();
    if (wid == 0 && lane < 8) {
        int w = wt[lane], wx = w;
        #pragma unroll
        for (int o = 1; o < 8; o <<= 1) {
            int tmp = __shfl_up_sync(0xFFu, wx, o);
            if (lane >= o) wx += tmp;
        }
        wt[lane] = wx - w;
    }
    __syncthreads();
    if (t < NBLK) g_bsum[t] = x - v + wt[wid];
}

__global__ void scan3_kernel(int E) {
    int idx = blockIdx.x * 256 + threadIdx.x;
    if (idx < NN) {
        int o = g_off[idx] + g_bsum[blockIdx.x];
        g_off[idx] = o;
        g_cur[idx] = o;
    }
    if (idx == 0) g_off[NN] = E;
}

__global__ void scatter_kernel(const int* __restrict__ src,
                               const int* __restrict__ dst, int E) {
    int i0 = (blockIdx.x * blockDim.x + threadIdx.x) * 4;
    #pragma unroll
    for (int j = 0; j < 4; j++) {
        int i = i0 + j;
        if (i < E) {
            int pos = atomicAdd(&g_cur[dst[i]], 1);
            g_ssrc[pos] = src[i];
        }
    }
}

// ---------------------------------------------------------------------------
// Tensor-core GEMM: C[N,Fout] = A[N,K] @ W[K,Fout], fp32 in/out.
// bf16 hi/lo split (3-term compensation), mma.sync.m16n8k16.
// Block tile 128 x TN, K-chunk 16, 8 warps (2 m x 4 n), warp tile 64 x TN/4.
// ---------------------------------------------------------------------------
__device__ __forceinline__ void ldsm_x4(unsigned* r, unsigned addr) {
    asm volatile("ldmatrix.sync.aligned.m8n8.x4.shared.b16 {%0,%1,%2,%3}, [%4];"
                 : "=r"(r[0]), "=r"(r[1]), "=r"(r[2]), "=r"(r[3]) : "r"(addr));
}
__device__ __forceinline__ void ldsm_x2(unsigned* r, unsigned addr) {
    asm volatile("ldmatrix.sync.aligned.m8n8.x2.shared.b16 {%0,%1}, [%2];"
                 : "=r"(r[0]), "=r"(r[1]) : "r"(addr));
}
__device__ __forceinline__ void mma_bf16(float* c, const unsigned* a, const unsigned* b) {
    asm volatile(
        "mma.sync.aligned.m16n8k16.row.col.f32.bf16.bf16.f32 "
        "{%0,%1,%2,%3}, {%4,%5,%6,%7}, {%8,%9}, {%0,%1,%2,%3};"
        : "+f"(c[0]), "+f"(c[1]), "+f"(c[2]), "+f"(c[3])
        : "r"(a[0]), "r"(a[1]), "r"(a[2]), "r"(a[3]), "r"(b[0]), "r"(b[1]));
}

template<int TN>
__global__ __launch_bounds__(256)
void gemm_tc_kernel(const float* __restrict__ Ain, long long a_off,
                    const float* __restrict__ W, long long c_off,
                    int N, int K, int Fout) {
    constexpr int TM = 128;
    constexpr int WTN = TN / 4;      // warp n tile (32 or 16)
    constexpr int MF = 4;            // 64 / 16
    constexpr int NF = WTN / 8;      // 4 or 2
    constexpr int PITCH = 24;        // bf16 row pitch (48B, conflict-free ldsm)

    const float* A = (a_off >= 0) ? (g_pool + a_off) : Ain;
    float* C = g_pool + c_off;

    __shared__ __align__(16) __nv_bfloat16 As[2][TM][PITCH];
    __shared__ __align__(16) __nv_bfloat16 Bs[2][TN][PITCH];

    int t = threadIdx.x;
    int lane = t & 31, wid = t >> 5;
    int warp_m = wid & 1, warp_n = wid >> 1;
    int m_off = warp_m * 64, n_off = warp_n * WTN;
    int row0 = blockIdx.x * TM;
    int col0 = blockIdx.y * TN;

    float c[MF][NF][4];
    #pragma unroll
    for (int i = 0; i < MF; i++)
        #pragma unroll
        for (int j = 0; j < NF; j++)
            #pragma unroll
            for (int q = 0; q < 4; q++) c[i][j][q] = 0.0f;

    // per-lane ldmatrix source addresses (row/col offsets fixed per lane)
    int g = lane >> 3, r = lane & 7;
    int a_row = (g & 1) * 8 + r;
    int a_col = (g >> 1) * 8;
    int b_row = r;
    int b_col = (g & 1) * 8;

    // A global load mapping: thread -> (m, k-octet)
    int am = t >> 1;
    int ak = (t & 1) * 8;

    for (int k0 = 0; k0 < K; k0 += 16) {
        // ---- load + convert A tile (128x16) ----
        {
            int grow = row0 + am;
            float4 v0 = make_float4(0.f, 0.f, 0.f, 0.f), v1 = v0;
            if (grow < N) {
                const float* ap = A + (size_t)grow * K + k0 + ak;
                v0 = *(const float4*)ap;
                v1 = *(const float4*)(ap + 4);
            }
            float vv[8] = {v0.x, v0.y, v0.z, v0.w, v1.x, v1.y, v1.z, v1.w};
            #pragma unroll
            for (int p = 0; p < 4; p++) {
                float x0 = vv[2 * p], x1 = vv[2 * p + 1];
                __nv_bfloat16 h0 = __float2bfloat16(x0);
                __nv_bfloat16 h1 = __float2bfloat16(x1);
                __nv_bfloat16 l0 = __float2bfloat16(x0 - __bfloat162float(h0));
                __nv_bfloat16 l1 = __float2bfloat16(x1 - __bfloat162float(h1));
                *(__nv_bfloat162*)&As[0][am][ak + 2 * p] = __nv_bfloat162(h0, h1);
                *(__nv_bfloat162*)&As[1][am][ak + 2 * p] = __nv_bfloat162(l0, l1);
            }
        }
        // ---- load + convert W tile (16 x TN), store transposed [n][k] ----
        {
            constexpr int NV4 = TN / 4;           // float4 per k-row
            constexpr int ITERS = (16 * NV4) / 256;
            #pragma unroll
            for (int it = 0; it < ITERS; it++) {
                int lin = t + it * 256;
                int kk = lin / NV4;
                int nq = (lin % NV4) * 4;
                float4 w = *(const float4*)(W + (size_t)(k0 + kk) * Fout + col0 + nq);
                float ww[4] = {w.x, w.y, w.z, w.w};
                #pragma unroll
                for (int j = 0; j < 4; j++) {
                    __nv_bfloat16 h = __float2bfloat16(ww[j]);
                    __nv_bfloat16 l = __float2bfloat16(ww[j] - __bfloat162float(h));
                    Bs[0][nq + j][kk] = h;
                    Bs[1][nq + j][kk] = l;
                }
            }
        }
        __syncthreads();

        // ---- fragment loads ----
        unsigned a_hi[MF][4], a_lo[MF][4], b_hi[NF][2], b_lo[NF][2];
        #pragma unroll
        for (int i = 0; i < MF; i++) {
            ldsm_x4(a_hi[i], (unsigned)__cvta_generic_to_shared(
                        &As[0][m_off + i * 16 + a_row][a_col]));
            ldsm_x4(a_lo[i], (unsigned)__cvta_generic_to_shared(
                        &As[1][m_off + i * 16 + a_row][a_col]));
        }
        #pragma unroll
        for (int j = 0; j < NF; j++) {
            ldsm_x2(b_hi[j], (unsigned)__cvta_generic_to_shared(
                        &Bs[0][n_off + j * 8 + b_row][b_col]));
            ldsm_x2(b_lo[j], (unsigned)__cvta_generic_to_shared(
                        &Bs[1][n_off + j * 8 + b_row][b_col]));
        }

        // ---- 3-term compensated MMA ----
        #pragma unroll
        for (int i = 0; i < MF; i++)
            #pragma unroll
            for (int j = 0; j < NF; j++) mma_bf16(c[i][j], a_hi[i], b_hi[j]);
        #pragma unroll
        for (int i = 0; i < MF; i++)
            #pragma unroll
            for (int j = 0; j < NF; j++) mma_bf16(c[i][j], a_hi[i], b_lo[j]);
        #pragma unroll
        for (int i = 0; i < MF; i++)
            #pragma unroll
            for (int j = 0; j < NF; j++) mma_bf16(c[i][j], a_lo[i], b_hi[j]);

        __syncthreads();
    }

    // ---- epilogue ----
    int lr = lane >> 2;
    int lc = (lane & 3) * 2;
    #pragma unroll
    for (int i = 0; i < MF; i++) {
        int gr = row0 + m_off + i * 16 + lr;
        #pragma unroll
        for (int j = 0; j < NF; j++) {
            int gc = col0 + n_off + j * 8 + lc;
            if (gr < N)
                *(float2*)(C + (size_t)gr * Fout + gc) = make_float2(c[i][j][0], c[i][j][1]);
            if (gr + 8 < N)
                *(float2*)(C + (size_t)(gr + 8) * Fout + gc) = make_float2(c[i][j][2], c[i][j][3]);
        }
    }
}

// ---------------------------------------------------------------------------
// Fused per-node kernel: one warp per dst node, single-pass online softmax.
// ---------------------------------------------------------------------------
__device__ __forceinline__ float lrelu(float z) {
    return z > 0.0f ? z : 0.2f * z;
}

template<int F, bool RELU>
__global__ __launch_bounds__(256)
void node_kernel(long long xl_off, long long xr_off,
                 const float* __restrict__ att,
                 const float* __restrict__ bias,
                 float* __restrict__ outp, long long out_off) {
    int node = (int)(((long long)blockIdx.x * blockDim.x + threadIdx.x) >> 5);
    int lane = threadIdx.x & 31;
    if (node >= NN) return;

    const float* xl = g_pool + xl_off;
    const float* xr = g_pool + xr_off;
    float* out = (out_off >= 0) ? (g_pool + out_off) : outp;

    int s0 = g_off[node], s1 = g_off[node + 1];

    if (F == 128) {
        float4 xr4 = *(const float4*)(xr + (size_t)node * F + lane * 4);
        float4 at4 = *(const float4*)(att + lane * 4);
        float4 acc = make_float4(0.f, 0.f, 0.f, 0.f);
        float m = -INFINITY, ssum = 0.0f;

        for (int base = s0; base < s1; base += 32) {
            int n = min(32, s1 - base);
            int sid = (base + lane < s1) ? g_ssrc[base + lane] : 0;
            for (int j = 0; j < n; j++) {
                int sj = __shfl_sync(0xFFFFFFFFu, sid, j);
                float4 a = *(const float4*)(xl + (size_t)sj * F + lane * 4);
                float part = lrelu(a.x + xr4.x) * at4.x + lrelu(a.y + xr4.y) * at4.y
                           + lrelu(a.z + xr4.z) * at4.z + lrelu(a.w + xr4.w) * at4.w;
                #pragma unroll
                for (int o = 16; o; o >>= 1)
                    part += __shfl_xor_sync(0xFFFFFFFFu, part, o);
                float e = part;
                if (e > m) {
                    float sc = __expf(m - e);
                    ssum = ssum * sc + 1.0f;
                    acc.x = acc.x * sc + a.x;  acc.y = acc.y * sc + a.y;
                    acc.z = acc.z * sc + a.z;  acc.w = acc.w * sc + a.w;
                    m = e;
                } else {
                    float w = __expf(e - m);
                    ssum += w;
                    acc.x += w * a.x; acc.y += w * a.y;
                    acc.z += w * a.z; acc.w += w * a.w;
                }
            }
        }
        float inv = 1.0f / (ssum + 1e-16f);
        float4 bb = *(const float4*)(bias + lane * 4);
        float4 o;
        o.x = acc.x * inv + bb.x; o.y = acc.y * inv + bb.y;
        o.z = acc.z * inv + bb.z; o.w = acc.w * inv + bb.w;
        if (RELU) {
            o.x = fmaxf(o.x, 0.f); o.y = fmaxf(o.y, 0.f);
            o.z = fmaxf(o.z, 0.f); o.w = fmaxf(o.w, 0.f);
        }
        *(float4*)(out + (size_t)node * F + lane * 4) = o;
    } else { // F == 64
        float2 xr2 = *(const float2*)(xr + (size_t)node * F + lane * 2);
        float2 at2 = *(const float2*)(att + lane * 2);
        float2 acc = make_float2(0.f, 0.f);
        float m = -INFINITY, ssum = 0.0f;

        for (int base = s0; base < s1; base += 32) {
            int n = min(32, s1 - base);
            int sid = (base + lane < s1) ? g_ssrc[base + lane] : 0;
            for (int j = 0; j < n; j++) {
                int sj = __shfl_sync(0xFFFFFFFFu, sid, j);
                float2 a = *(const float2*)(xl + (size_t)sj * F + lane * 2);
                float part = lrelu(a.x + xr2.x) * at2.x + lrelu(a.y + xr2.y) * at2.y;
                #pragma unroll
                for (int o = 16; o; o >>= 1)
                    part += __shfl_xor_sync(0xFFFFFFFFu, part, o);
                float e = part;
                if (e > m) {
                    float sc = __expf(m - e);
                    ssum = ssum * sc + 1.0f;
                    acc.x = acc.x * sc + a.x;
                    acc.y = acc.y * sc + a.y;
                    m = e;
                } else {
                    float w = __expf(e - m);
                    ssum += w;
                    acc.x += w * a.x; acc.y += w * a.y;
                }
            }
        }
        float inv = 1.0f / (ssum + 1e-16f);
        float2 bb = *(const float2*)(bias + lane * 2);
        float2 o;
        o.x = acc.x * inv + bb.x; o.y = acc.y * inv + bb.y;
        if (RELU) { o.x = fmaxf(o.x, 0.f); o.y = fmaxf(o.y, 0.f); }
        *(float2*)(out + (size_t)node * F + lane * 2) = o;
    }
}

// ---------------------------------------------------------------------------
// Host launch
// ---------------------------------------------------------------------------
extern "C" void kernel_launch(void* const* d_in, const int* in_sizes, int n_in,
                              void* d_out, int out_size) {
    const float* x    = (const float*)d_in[0];
    const int*   ei   = (const int*)d_in[1];
    const float* Wl1  = (const float*)d_in[2];
    const float* Wr1  = (const float*)d_in[3];
    const float* att1 = (const float*)d_in[4];
    const float* b1   = (const float*)d_in[5];
    const float* Wl2  = (const float*)d_in[6];
    const float* Wr2  = (const float*)d_in[7];
    const float* att2 = (const float*)d_in[8];
    const float* b2   = (const float*)d_in[9];
    float* out = (float*)d_out;

    int E = in_sizes[1] / 2;
    const int* srcp = ei;
    const int* dstp = ei + E;

    int eBlocks4 = (E + 1023) / 1024;
    int nodeWarpBlocks = (NN * 32 + 255) / 256;

    // ---- CSR build ----
    zero_cnt_kernel<<<NBLK, 256>>>();
    hist_kernel<<<eBlocks4, 256>>>(dstp, E);
    scan1_kernel<<<NBLK, 256>>>();
    scan2_kernel<<<1, 256>>>();
    scan3_kernel<<<NBLK, 256>>>(E);
    scatter_kernel<<<eBlocks4, 256>>>(srcp, dstp, E);

    // ---- Layer 1 ----
    {
        dim3 grid((NN + 127) / 128, HH / 128);
        gemm_tc_kernel<128><<<grid, 256>>>(x, -1, Wl1, OFF_XL1, NN, FIN, HH);
        gemm_tc_kernel<128><<<grid, 256>>>(x, -1, Wr1, OFF_XR1, NN, FIN, HH);
    }
    node_kernel<128, true><<<nodeWarpBlocks, 256>>>(OFF_XL1, OFF_XR1, att1, b1,
                                                    nullptr, OFF_H);

    // ---- Layer 2 ----
    {
        dim3 grid((NN + 127) / 128, CC / 64);
        gemm_tc_kernel<64><<<grid, 256>>>(nullptr, OFF_H, Wl2, OFF_XL2, NN, HH, CC);
        gemm_tc_kernel<64><<<grid, 256>>>(nullptr, OFF_H, Wr2, OFF_XR2, NN, HH, CC);
    }
    node_kernel<64, false><<<nodeWarpBlocks, 256>>>(OFF_XL2, OFF_XR2, att2, b2,
                                                    out, -1);
}

// round 4
// speedup vs baseline: 3.2341x; 1.4265x over previous
#include <cuda_runtime.h>
#include <cuda_bf16.h>
#include <math.h>

// ---------------------------------------------------------------------------
// Problem constants
// ---------------------------------------------------------------------------
#define NN   50000
#define FIN  256
#define HH   128
#define CC   64
#define EMAX 1600000
#define NBLK 196              // ceil(NN/256)

// ---------------------------------------------------------------------------
// Static scratch
// ---------------------------------------------------------------------------
constexpr long long OFF_XL1 = 0;
constexpr long long OFF_XR1 = (long long)NN * HH;
constexpr long long OFF_XL2 = 2LL * NN * HH;
constexpr long long OFF_XR2 = OFF_XL2 + (long long)NN * CC;
constexpr long long POOL_SZ = OFF_XR2 + (long long)NN * CC;

__device__ float g_pool[POOL_SZ];

// bf16 hi/lo operand storage
__device__ __nv_bfloat16 g_xhi[(long long)NN * FIN];
__device__ __nv_bfloat16 g_xlo[(long long)NN * FIN];
__device__ __nv_bfloat16 g_hhi[(long long)NN * HH];
__device__ __nv_bfloat16 g_hlo[(long long)NN * HH];
// packed weights: W1L @0 (32768), W1R @32768, W2L @65536 (8192), W2R @73728
__device__ __nv_bfloat16 g_whi[81920];
__device__ __nv_bfloat16 g_wlo[81920];

__device__ int g_cnt[NN];
__device__ int g_off[NN + 1];
__device__ int g_cur[NN];
__device__ int g_bsum[256];
__device__ int g_ssrc[EMAX];

// ---------------------------------------------------------------------------
// fp32 -> bf16 hi/lo conversion
// ---------------------------------------------------------------------------
__global__ void cvt_kernel(const float* __restrict__ src, int sel,
                           long long doff, long long n) {
    __nv_bfloat16* hi = sel ? g_whi : g_xhi;
    __nv_bfloat16* lo = sel ? g_wlo : g_xlo;
    long long i = ((long long)blockIdx.x * blockDim.x + threadIdx.x) * 4;
    if (i >= n) return;
    float4 v = *(const float4*)(src + i);
    float vv[4] = {v.x, v.y, v.z, v.w};
    __nv_bfloat16 h[4], l[4];
    #pragma unroll
    for (int j = 0; j < 4; j++) {
        h[j] = __float2bfloat16(vv[j]);
        l[j] = __float2bfloat16(vv[j] - __bfloat162float(h[j]));
    }
    *(__nv_bfloat162*)(hi + doff + i)     = __nv_bfloat162(h[0], h[1]);
    *(__nv_bfloat162*)(hi + doff + i + 2) = __nv_bfloat162(h[2], h[3]);
    *(__nv_bfloat162*)(lo + doff + i)     = __nv_bfloat162(l[0], l[1]);
    *(__nv_bfloat162*)(lo + doff + i + 2) = __nv_bfloat162(l[2], l[3]);
}

// ---------------------------------------------------------------------------
// CSR construction
// ---------------------------------------------------------------------------
__global__ void zero_cnt_kernel() {
    int i = blockIdx.x * blockDim.x + threadIdx.x;
    if (i < NN) g_cnt[i] = 0;
}

__global__ void hist_kernel(const int* __restrict__ dst, int E) {
    int i0 = (blockIdx.x * blockDim.x + threadIdx.x) * 4;
    #pragma unroll
    for (int j = 0; j < 4; j++) {
        int i = i0 + j;
        if (i < E) atomicAdd(&g_cnt[dst[i]], 1);
    }
}

__global__ void scan1_kernel() {
    __shared__ int wt[8];
    int t = threadIdx.x, lane = t & 31, wid = t >> 5;
    int idx = blockIdx.x * 256 + t;
    int v = (idx < NN) ? g_cnt[idx] : 0;
    int x = v;
    #pragma unroll
    for (int o = 1; o < 32; o <<= 1) {
        int tmp = __shfl_up_sync(0xFFFFFFFFu, x, o);
        if (lane >= o) x += tmp;
    }
    if (lane == 31) wt[wid] = x;
    __syncthreads();
    if (wid == 0 && lane < 8) {
        int w = wt[lane], wx = w;
        #pragma unroll
        for (int o = 1; o < 8; o <<= 1) {
            int tmp = __shfl_up_sync(0xFFu, wx, o);
            if (lane >= o) wx += tmp;
        }
        wt[lane] = wx - w;
    }
    __syncthreads();
    int excl = x - v + wt[wid];
    if (idx < NN) g_off[idx] = excl;
    if (t == 255) g_bsum[blockIdx.x] = excl + v;
}

__global__ void scan2_kernel() {
    __shared__ int wt[8];
    int t = threadIdx.x, lane = t & 31, wid = t >> 5;
    int v = (t < NBLK) ? g_bsum[t] : 0;
    int x = v;
    #pragma unroll
    for (int o = 1; o < 32; o <<= 1) {
        int tmp = __shfl_up_sync(0xFFFFFFFFu, x, o);
        if (lane >= o) x += tmp;
    }
    if (lane == 31) wt[wid] = x;
    __syncthreads();
    if (wid == 0 && lane < 8) {
        int w = wt[lane], wx = w;
        #pragma unroll
        for (int o = 1; o < 8; o <<= 1) {
            int tmp = __shfl_up_sync(0xFFu, wx, o);
            if (lane >= o) wx += tmp;
        }
        wt[lane] = wx - w;
    }
    __syncthreads();
    if (t < NBLK) g_bsum[t] = x - v + wt[wid];
}

__global__ void scan3_kernel(int E) {
    int idx = blockIdx.x * 256 + threadIdx.x;
    if (idx < NN) {
        int o = g_off[idx] + g_bsum[blockIdx.x];
        g_off[idx] = o;
        g_cur[idx] = o;
    }
    if (idx == 0) g_off[NN] = E;
}

__global__ void scatter_kernel(const int* __restrict__ src,
                               const int* __restrict__ dst, int E) {
    int i0 = (blockIdx.x * blockDim.x + threadIdx.x) * 4;
    #pragma unroll
    for (int j = 0; j < 4; j++) {
        int i = i0 + j;
        if (i < E) {
            int pos = atomicAdd(&g_cur[dst[i]], 1);
            g_ssrc[pos] = src[i];
        }
    }
}

// ---------------------------------------------------------------------------
// Tensor-core GEMM on precomputed bf16 hi/lo. cp.async double-buffered.
// C[N,Fout] = A @ W. Tile 128 x TN, BK=16, 8 warps (2m x 4n).
// ---------------------------------------------------------------------------
__device__ __forceinline__ void ldsm_x4(unsigned* r, unsigned addr) {
    asm volatile("ldmatrix.sync.aligned.m8n8.x4.shared.b16 {%0,%1,%2,%3}, [%4];"
                 : "=r"(r[0]), "=r"(r[1]), "=r"(r[2]), "=r"(r[3]) : "r"(addr));
}
__device__ __forceinline__ void ldsm_x2t(unsigned* r, unsigned addr) {
    asm volatile("ldmatrix.sync.aligned.m8n8.x2.trans.shared.b16 {%0,%1}, [%2];"
                 : "=r"(r[0]), "=r"(r[1]) : "r"(addr));
}
__device__ __forceinline__ void mma_bf16(float* c, const unsigned* a, const unsigned* b) {
    asm volatile(
        "mma.sync.aligned.m16n8k16.row.col.f32.bf16.bf16.f32 "
        "{%0,%1,%2,%3}, {%4,%5,%6,%7}, {%8,%9}, {%0,%1,%2,%3};"
        : "+f"(c[0]), "+f"(c[1]), "+f"(c[2]), "+f"(c[3])
        : "r"(a[0]), "r"(a[1]), "r"(a[2]), "r"(a[3]), "r"(b[0]), "r"(b[1]));
}
__device__ __forceinline__ void cp16(unsigned dst, const void* src, bool valid) {
    int sz = valid ? 16 : 0;
    asm volatile("cp.async.cg.shared.global [%0], [%1], 16, %2;"
                 :: "r"(dst), "l"(src), "r"(sz));
}
#define CP_COMMIT() asm volatile("cp.async.commit_group;")
#define CP_WAIT1()  asm volatile("cp.async.wait_group 1;")

template<int TN>
__global__ __launch_bounds__(256)
void gemm_tc_kernel(int a_sel, int K, long long w_off, long long c_off, int Fout) {
    constexpr int TM = 128, BK = 16;
    constexpr int APITCH = 24;          // bf16; 48B rows, conflict-free ldsm
    constexpr int BPITCH = TN + 8;      // k-major rows, conflict-free trans ldsm
    constexpr int NF = TN / 32;         // 4 or 2 (warp n tile = TN/4)

    const __nv_bfloat16* Ahi = a_sel ? g_hhi : g_xhi;
    const __nv_bfloat16* Alo = a_sel ? g_hlo : g_xlo;
    const __nv_bfloat16* Whi = g_whi + w_off;
    const __nv_bfloat16* Wlo = g_wlo + w_off;
    float* C = g_pool + c_off;

    __shared__ __align__(16) __nv_bfloat16 Ah[2][TM][APITCH];
    __shared__ __align__(16) __nv_bfloat16 Al[2][TM][APITCH];
    __shared__ __align__(16) __nv_bfloat16 Bh[2][BK][BPITCH];
    __shared__ __align__(16) __nv_bfloat16 Bl[2][BK][BPITCH];

    int t = threadIdx.x;
    int lane = t & 31, wid = t >> 5;
    int warp_m = wid & 1, warp_n = wid >> 1;
    int m_off = warp_m * 64, n_off = warp_n * (TN / 4);
    int row0 = blockIdx.x * TM;
    int col0 = blockIdx.y * TN;
    int N = NN;

    float c[4][NF][4];
    #pragma unroll
    for (int i = 0; i < 4; i++)
        #pragma unroll
        for (int j = 0; j < NF; j++)
            #pragma unroll
            for (int q = 0; q < 4; q++) c[i][j][q] = 0.0f;

    // ldmatrix lane mappings
    int g = lane >> 3, r = lane & 7;
    int a_row = (g & 1) * 8 + r;
    int a_col = (g >> 1) * 8;
    int b_krow = lane & 15;

    // A load mapping: thread -> (row, 16B chunk)
    int am = t >> 1;
    int ac = (t & 1) * 8;

    const int NIT = K / BK;

    auto load_stage = [&](int it, int s) {
        int k0 = it * BK;
        // A hi/lo
        int grow = row0 + am;
        bool v = grow < N;
        const __nv_bfloat16* gah = Ahi + (size_t)grow * K + k0 + ac;
        const __nv_bfloat16* gal = Alo + (size_t)grow * K + k0 + ac;
        cp16((unsigned)__cvta_generic_to_shared(&Ah[s][am][ac]), gah, v);
        cp16((unsigned)__cvta_generic_to_shared(&Al[s][am][ac]), gal, v);
        // B hi/lo (k-major, coalesced)
        if (TN == 128) {
            int kk = t >> 4, ch = (t & 15) * 8;
            const __nv_bfloat16* gbh = Whi + (size_t)(k0 + kk) * Fout + col0 + ch;
            const __nv_bfloat16* gbl = Wlo + (size_t)(k0 + kk) * Fout + col0 + ch;
            cp16((unsigned)__cvta_generic_to_shared(&Bh[s][kk][ch]), gbh, true);
            cp16((unsigned)__cvta_generic_to_shared(&Bl[s][kk][ch]), gbl, true);
        } else { // TN == 64
            if (t < 128) {
                int kk = t >> 3, ch = (t & 7) * 8;
                const __nv_bfloat16* gbh = Whi + (size_t)(k0 + kk) * Fout + col0 + ch;
                const __nv_bfloat16* gbl = Wlo + (size_t)(k0 + kk) * Fout + col0 + ch;
                cp16((unsigned)__cvta_generic_to_shared(&Bh[s][kk][ch]), gbh, true);
                cp16((unsigned)__cvta_generic_to_shared(&Bl[s][kk][ch]), gbl, true);
            }
        }
    };

    load_stage(0, 0);
    CP_COMMIT();

    for (int it = 0; it < NIT; it++) {
        if (it + 1 < NIT) load_stage(it + 1, (it + 1) & 1);
        CP_COMMIT();
        CP_WAIT1();
        __syncthreads();

        int s = it & 1;
        unsigned ah[4][4], bh[NF][2];
        #pragma unroll
        for (int i = 0; i < 4; i++)
            ldsm_x4(ah[i], (unsigned)__cvta_generic_to_shared(
                        &Ah[s][m_off + i * 16 + a_row][a_col]));
        #pragma unroll
        for (int j = 0; j < NF; j++)
            ldsm_x2t(bh[j], (unsigned)__cvta_generic_to_shared(
                        &Bh[s][b_krow][n_off + j * 8]));
        #pragma unroll
        for (int i = 0; i < 4; i++)
            #pragma unroll
            for (int j = 0; j < NF; j++) mma_bf16(c[i][j], ah[i], bh[j]);

        unsigned bl[NF][2];
        #pragma unroll
        for (int j = 0; j < NF; j++)
            ldsm_x2t(bl[j], (unsigned)__cvta_generic_to_shared(
                        &Bl[s][b_krow][n_off + j * 8]));
        #pragma unroll
        for (int i = 0; i < 4; i++)
            #pragma unroll
            for (int j = 0; j < NF; j++) mma_bf16(c[i][j], ah[i], bl[j]);

        unsigned al[4][4];
        #pragma unroll
        for (int i = 0; i < 4; i++)
            ldsm_x4(al[i], (unsigned)__cvta_generic_to_shared(
                        &Al[s][m_off + i * 16 + a_row][a_col]));
        #pragma unroll
        for (int i = 0; i < 4; i++)
            #pragma unroll
            for (int j = 0; j < NF; j++) mma_bf16(c[i][j], al[i], bh[j]);

        __syncthreads();
    }

    // epilogue
    int lr = lane >> 2;
    int lc = (lane & 3) * 2;
    #pragma unroll
    for (int i = 0; i < 4; i++) {
        int gr = row0 + m_off + i * 16 + lr;
        #pragma unroll
        for (int j = 0; j < NF; j++) {
            int gc = col0 + n_off + j * 8 + lc;
            if (gr < N)
                *(float2*)(C + (size_t)gr * Fout + gc) = make_float2(c[i][j][0], c[i][j][1]);
            if (gr + 8 < N)
                *(float2*)(C + (size_t)(gr + 8) * Fout + gc) = make_float2(c[i][j][2], c[i][j][3]);
        }
    }
}

// ---------------------------------------------------------------------------
// Fused per-node kernel: warp per node, branchless online softmax.
// ---------------------------------------------------------------------------
__device__ __forceinline__ float lrelu(float z) {
    return z > 0.0f ? z : 0.2f * z;
}

template<int F, bool RELU, bool EMIT_BF16>
__global__ __launch_bounds__(256)
void node_kernel(long long xl_off, long long xr_off,
                 const float* __restrict__ att,
                 const float* __restrict__ bias,
                 float* __restrict__ outp) {
    int node = (int)(((long long)blockIdx.x * blockDim.x + threadIdx.x) >> 5);
    int lane = threadIdx.x & 31;
    if (node >= NN) return;

    const float* xl = g_pool + xl_off;
    const float* xr = g_pool + xr_off;

    int s0 = g_off[node], s1 = g_off[node + 1];

    if (F == 128) {
        float4 xr4 = *(const float4*)(xr + (size_t)node * F + lane * 4);
        float4 at4 = *(const float4*)(att + lane * 4);
        float4 acc = make_float4(0.f, 0.f, 0.f, 0.f);
        float m = -INFINITY, ssum = 0.0f;

        for (int base = s0; base < s1; base += 32) {
            int n = min(32, s1 - base);
            int sid = (base + lane < s1) ? g_ssrc[base + lane] : 0;
            for (int j = 0; j < n; j++) {
                int sj = __shfl_sync(0xFFFFFFFFu, sid, j);
                float4 a = *(const float4*)(xl + (size_t)sj * F + lane * 4);
                float part = lrelu(a.x + xr4.x) * at4.x + lrelu(a.y + xr4.y) * at4.y
                           + lrelu(a.z + xr4.z) * at4.z + lrelu(a.w + xr4.w) * at4.w;
                #pragma unroll
                for (int o = 16; o; o >>= 1)
                    part += __shfl_xor_sync(0xFFFFFFFFu, part, o);
                float e = part;
                float nm = fmaxf(m, e);
                float sc = __expf(m - nm);
                float w  = __expf(e - nm);
                ssum = ssum * sc + w;
                acc.x = acc.x * sc + w * a.x;  acc.y = acc.y * sc + w * a.y;
                acc.z = acc.z * sc + w * a.z;  acc.w = acc.w * sc + w * a.w;
                m = nm;
            }
        }
        float inv = 1.0f / (ssum + 1e-16f);
        float4 bb = *(const float4*)(bias + lane * 4);
        float v0 = acc.x * inv + bb.x, v1 = acc.y * inv + bb.y;
        float v2 = acc.z * inv + bb.z, v3 = acc.w * inv + bb.w;
        if (RELU) {
            v0 = fmaxf(v0, 0.f); v1 = fmaxf(v1, 0.f);
            v2 = fmaxf(v2, 0.f); v3 = fmaxf(v3, 0.f);
        }
        if (EMIT_BF16) {
            size_t o = (size_t)node * F + lane * 4;
            __nv_bfloat16 h0 = __float2bfloat16(v0), h1 = __float2bfloat16(v1);
            __nv_bfloat16 h2 = __float2bfloat16(v2), h3 = __float2bfloat16(v3);
            *(__nv_bfloat162*)(g_hhi + o)     = __nv_bfloat162(h0, h1);
            *(__nv_bfloat162*)(g_hhi + o + 2) = __nv_bfloat162(h2, h3);
            *(__nv_bfloat162*)(g_hlo + o) = __nv_bfloat162(
                __float2bfloat16(v0 - __bfloat162float(h0)),
                __float2bfloat16(v1 - __bfloat162float(h1)));
            *(__nv_bfloat162*)(g_hlo + o + 2) = __nv_bfloat162(
                __float2bfloat16(v2 - __bfloat162float(h2)),
                __float2bfloat16(v3 - __bfloat162float(h3)));
        } else {
            *(float4*)(outp + (size_t)node * F + lane * 4) = make_float4(v0, v1, v2, v3);
        }
    } else { // F == 64
        float2 xr2 = *(const float2*)(xr + (size_t)node * F + lane * 2);
        float2 at2 = *(const float2*)(att + lane * 2);
        float2 acc = make_float2(0.f, 0.f);
        float m = -INFINITY, ssum = 0.0f;

        for (int base = s0; base < s1; base += 32) {
            int n = min(32, s1 - base);
            int sid = (base + lane < s1) ? g_ssrc[base + lane] : 0;
            for (int j = 0; j < n; j++) {
                int sj = __shfl_sync(0xFFFFFFFFu, sid, j);
                float2 a = *(const float2*)(xl + (size_t)sj * F + lane * 2);
                float part = lrelu(a.x + xr2.x) * at2.x + lrelu(a.y + xr2.y) * at2.y;
                #pragma unroll
                for (int o = 16; o; o >>= 1)
                    part += __shfl_xor_sync(0xFFFFFFFFu, part, o);
                float e = part;
                float nm = fmaxf(m, e);
                float sc = __expf(m - nm);
                float w  = __expf(e - nm);
                ssum = ssum * sc + w;
                acc.x = acc.x * sc + w * a.x;
                acc.y = acc.y * sc + w * a.y;
                m = nm;
            }
        }
        float inv = 1.0f / (ssum + 1e-16f);
        float2 bb = *(const float2*)(bias + lane * 2);
        float v0 = acc.x * inv + bb.x, v1 = acc.y * inv + bb.y;
        if (RELU) { v0 = fmaxf(v0, 0.f); v1 = fmaxf(v1, 0.f); }
        *(float2*)(outp + (size_t)node * F + lane * 2) = make_float2(v0, v1);
    }
}

// ---------------------------------------------------------------------------
// Host launch (event fork/join for capture-safe multi-stream overlap)
// ---------------------------------------------------------------------------
extern "C" void kernel_launch(void* const* d_in, const int* in_sizes, int n_in,
                              void* d_out, int out_size) {
    const float* x    = (const float*)d_in[0];
    const int*   ei   = (const int*)d_in[1];
    const float* Wl1  = (const float*)d_in[2];
    const float* Wr1  = (const float*)d_in[3];
    const float* att1 = (const float*)d_in[4];
    const float* b1   = (const float*)d_in[5];
    const float* Wl2  = (const float*)d_in[6];
    const float* Wr2  = (const float*)d_in[7];
    const float* att2 = (const float*)d_in[8];
    const float* b2   = (const float*)d_in[9];
    float* out = (float*)d_out;

    int E = in_sizes[1] / 2;
    const int* srcp = ei;
    const int* dstp = ei + E;

    static cudaStream_t s2 = nullptr, s3 = nullptr;
    static cudaEvent_t e_fork, e_x, e_csr, e_r1, e_n1, e_r2;
    if (!s2) {
        cudaStreamCreateWithFlags(&s2, cudaStreamNonBlocking);
        cudaStreamCreateWithFlags(&s3, cudaStreamNonBlocking);
        cudaEventCreateWithFlags(&e_fork, cudaEventDisableTiming);
        cudaEventCreateWithFlags(&e_x,    cudaEventDisableTiming);
        cudaEventCreateWithFlags(&e_csr,  cudaEventDisableTiming);
        cudaEventCreateWithFlags(&e_r1,   cudaEventDisableTiming);
        cudaEventCreateWithFlags(&e_n1,   cudaEventDisableTiming);
        cudaEventCreateWithFlags(&e_r2,   cudaEventDisableTiming);
    }

    cudaStream_t m = 0;  // legacy default (capture) stream
    int eBlocks4 = (E + 1023) / 1024;
    int nodeWarpBlocks = (NN * 32 + 255) / 256;

    cudaEventRecord(e_fork, m);
    cudaStreamWaitEvent(s2, e_fork, 0);
    cudaStreamWaitEvent(s3, e_fork, 0);

    // ---- s2: CSR build ----
    zero_cnt_kernel<<<NBLK, 256, 0, s2>>>();
    hist_kernel<<<eBlocks4, 256, 0, s2>>>(dstp, E);
    scan1_kernel<<<NBLK, 256, 0, s2>>>();
    scan2_kernel<<<1, 256, 0, s2>>>();
    scan3_kernel<<<NBLK, 256, 0, s2>>>(E);
    scatter_kernel<<<eBlocks4, 256, 0, s2>>>(srcp, dstp, E);
    cudaEventRecord(e_csr, s2);

    // ---- s3: Wr1 / W2 converts ----
    cvt_kernel<<<32, 256, 0, s3>>>(Wr1, 1, 32768, 32768);
    cvt_kernel<<<8,  256, 0, s3>>>(Wl2, 1, 65536, 8192);
    cvt_kernel<<<8,  256, 0, s3>>>(Wr2, 1, 73728, 8192);

    // ---- main: x + Wl1 converts, Wl1 GEMM ----
    cvt_kernel<<<(int)(((long long)NN * FIN / 4 + 255) / 256), 256, 0, m>>>(
        x, 0, 0, (long long)NN * FIN);
    cudaEventRecord(e_x, m);
    cvt_kernel<<<32, 256, 0, m>>>(Wl1, 1, 0, 32768);
    gemm_tc_kernel<128><<<dim3((NN + 127) / 128, 1), 256, 0, m>>>(
        0, FIN, 0, OFF_XL1, HH);

    // ---- s3: Wr1 GEMM (after x convert) ----
    cudaStreamWaitEvent(s3, e_x, 0);
    gemm_tc_kernel<128><<<dim3((NN + 127) / 128, 1), 256, 0, s3>>>(
        0, FIN, 32768, OFF_XR1, HH);
    cudaEventRecord(e_r1, s3);

    // ---- main: node1 (emits h as bf16 hi/lo) ----
    cudaStreamWaitEvent(m, e_r1, 0);
    cudaStreamWaitEvent(m, e_csr, 0);
    node_kernel<128, true, true><<<nodeWarpBlocks, 256, 0, m>>>(
        OFF_XL1, OFF_XR1, att1, b1, nullptr);
    cudaEventRecord(e_n1, m);

    // ---- layer 2 GEMMs (Wl2 on main, Wr2 on s3) ----
    gemm_tc_kernel<64><<<dim3((NN + 127) / 128, 1), 256, 0, m>>>(
        1, HH, 65536, OFF_XL2, CC);
    cudaStreamWaitEvent(s3, e_n1, 0);
    gemm_tc_kernel<64><<<dim3((NN + 127) / 128, 1), 256, 0, s3>>>(
        1, HH, 73728, OFF_XR2, CC);
    cudaEventRecord(e_r2, s3);

    // ---- main: node2 -> out ----
    cudaStreamWaitEvent(m, e_r2, 0);
    node_kernel<64, false, false><<<nodeWarpBlocks, 256, 0, m>>>(
        OFF_XL2, OFF_XR2, att2, b2, out);
}